// round 14
// baseline (speedup 1.0000x reference)
#include <cuda_runtime.h>
#include <math.h>

#define Nn 100000
#define Ee 3200000
#define Ff 128
#define Hh 16
#define Cc 10
#define Kk1 25000
#define Kk2 6250
#define G1 64     // topk1 persistent grid
#define G2 32     // topk2 persistent grid

// ---------------- scratch ------------------------------------------------------
__device__ __align__(16) float d_h0[Nn * Hh];   // x@W1, then scaled by dinv
__device__ __align__(16) float d_h[Nn * Hh];    // conv1 edge accumulator (memset 0)
__device__ float d_dinv[Nn];
__device__ int d_deg[Nn];                        // memset 0
__device__ float d_t[Nn];
__device__ float d_score[Nn];
__device__ unsigned long long d_key[Nn];
__device__ int d_perm[Kk1];
__device__ int d_deg2[Nn];
__device__ float d_dinv2[Nn];
__device__ __align__(16) float d_x1[Kk1 * Hh];
__device__ __align__(16) float d_g0[Nn * 16];
__device__ __align__(16) float d_h2[Nn * 16];
__device__ float d_t2[Nn];
__device__ float d_score2[Nn];
__device__ unsigned long long d_eplist[Ee];

// one zeroed blob: hist[8][8192] | selbit[3136] | state[8] | acc[10]
__device__ __align__(16) unsigned d_blob[68696];
#define HIST(p) (d_blob + (p) * 8192)
#define D_SELBIT (d_blob + 65536)
#define D_STATE (d_blob + 68672)   // 0:bar1 1:bar2 2:permcnt 3:ecnt 4:tick
#define D_ACC ((float*)(d_blob + 68680))

__device__ __forceinline__ void red_v4(float* p, float4 v) {
    asm volatile("red.global.add.v4.f32 [%0], {%1,%2,%3,%4};"
                 :: "l"(p), "f"(v.x), "f"(v.y), "f"(v.z), "f"(v.w) : "memory");
}
__device__ __forceinline__ unsigned f2u(float f) {
    unsigned u = __float_as_uint(f);
    return (u & 0x80000000u) ? ~u : (u | 0x80000000u);
}
__device__ __forceinline__ unsigned long long fma2(unsigned long long a,
                                                   unsigned long long b,
                                                   unsigned long long c) {
    unsigned long long r;
    asm("fma.rn.f32x2 %0, %1, %2, %3;" : "=l"(r) : "l"(a), "l"(b), "l"(c));
    return r;
}
__device__ __forceinline__ unsigned long long add2(unsigned long long a,
                                                   unsigned long long b) {
    unsigned long long r;
    asm("add.rn.f32x2 %0, %1, %2;" : "=l"(r) : "l"(a), "l"(b));
    return r;
}
__device__ __forceinline__ unsigned long long pack2(float v) {
    unsigned long long r;
    asm("mov.b64 %0, {%1, %1};" : "=l"(r) : "f"(v));
    return r;
}

// ---------------- fused: h0 = x @ W1 (f32x2 packed)  ||  deg count -------------
#define MM1_BLOCKS 1536
#define DEG_BLOCKS 1024
__global__ void k_front(const float* __restrict__ x, const float* __restrict__ W1,
                        const int* __restrict__ dst) {
    if (blockIdx.x < MM1_BLOCKS) {
        __shared__ float Ws[Ff * Hh];
        for (int i = threadIdx.x; i < Ff * Hh; i += blockDim.x) Ws[i] = W1[i];
        __syncthreads();
        int lane = threadIdx.x & 31;
        for (int node = blockIdx.x * 8 + (threadIdx.x >> 5); node < Nn;
             node += MM1_BLOCKS * 8) {
            const float* xr = x + (size_t)node * Ff;
            unsigned long long acc2[8];
#pragma unroll
            for (int j = 0; j < 8; j++) acc2[j] = 0ull;
#pragma unroll
            for (int c = 0; c < 4; c++) {
                int f = c * 32 + lane;
                unsigned long long xx = pack2(xr[f]);
                const unsigned long long* wr2 =
                    (const unsigned long long*)(Ws + f * Hh);
#pragma unroll
                for (int j = 0; j < 8; j++) acc2[j] = fma2(wr2[j], xx, acc2[j]);
            }
            // column-pair folding
            {
                bool hi = (lane & 16) != 0;
#pragma unroll
                for (int j = 0; j < 4; j++) {
                    unsigned long long sent = hi ? acc2[j] : acc2[j + 4];
                    unsigned long long recv = __shfl_xor_sync(0xFFFFFFFFu, sent, 16);
                    acc2[j] = add2(hi ? acc2[j + 4] : acc2[j], recv);
                }
            }
            {
                bool hi = (lane & 8) != 0;
#pragma unroll
                for (int j = 0; j < 2; j++) {
                    unsigned long long sent = hi ? acc2[j] : acc2[j + 2];
                    unsigned long long recv = __shfl_xor_sync(0xFFFFFFFFu, sent, 8);
                    acc2[j] = add2(hi ? acc2[j + 2] : acc2[j], recv);
                }
            }
            {
                bool hi = (lane & 4) != 0;
                unsigned long long sent = hi ? acc2[0] : acc2[1];
                unsigned long long recv = __shfl_xor_sync(0xFFFFFFFFu, sent, 4);
                acc2[0] = add2(hi ? acc2[1] : acc2[0], recv);
            }
            acc2[0] = add2(acc2[0], __shfl_xor_sync(0xFFFFFFFFu, acc2[0], 2));
            acc2[0] = add2(acc2[0], __shfl_xor_sync(0xFFFFFFFFu, acc2[0], 1));
            int pr = (lane >> 2) & 7;
            if ((lane & 3) == 0)
                ((unsigned long long*)(d_h0 + (size_t)node * Hh))[pr] = acc2[0];
        }
    } else {
        for (int e = (blockIdx.x - MM1_BLOCKS) * 256 + threadIdx.x; e < Ee;
             e += DEG_BLOCKS * 256)
            atomicAdd(&d_deg[dst[e]], 1);
    }
}

// dinv + pre-scale h0 (2 threads per node)
__global__ void k_dinv() {
    int gid = blockIdx.x * blockDim.x + threadIdx.x;
    int i = gid >> 1, half = gid & 1;
    bool valid = i < Nn;
    if (!valid) i = Nn - 1;
    float di = rsqrtf((float)d_deg[i] + 1.0f);
    if (valid && half == 0) d_dinv[i] = di;
    float4* h0 = (float4*)&d_h0[i * Hh];
#pragma unroll
    for (int qq = 0; qq < 2; qq++) {
        int q = half * 2 + qq;
        float4 v = h0[q];
        v.x *= di; v.y *= di; v.z *= di; v.w *= di;
        if (valid) h0[q] = v;
    }
}

__global__ void k_scat1(const int* __restrict__ src, const int* __restrict__ dst) {
    int t = blockIdx.x * blockDim.x + threadIdx.x;
    int e = t >> 2, q = t & 3;
    int s = src[e], d = dst[e];
    float4 v = *(const float4*)&d_h0[s * Hh + q * 4];
    red_v4(&d_h[d * Hh + q * 4], v);
}

// finalize conv1 (2 threads per node)
__global__ void k_prep1(const float* __restrict__ b1, const float* __restrict__ wroot,
                        const float* __restrict__ wrel, const float* __restrict__ pb) {
    int gid = blockIdx.x * blockDim.x + threadIdx.x;
    int i = gid >> 1, half = gid & 1;
    bool valid = i < Nn;
    if (!valid) i = Nn - 1;
    float di = d_dinv[i];
    float4* h = (float4*)&d_h[i * Hh];
    const float4* h0 = (const float4*)&d_h0[i * Hh];
    float sr = 0.f, st = 0.f;
#pragma unroll
    for (int qq = 0; qq < 2; qq++) {
        int q = half * 2 + qq;
        float4 a = h[q], s0 = h0[q];
        float4 b = __ldg(&((const float4*)b1)[q]);
        float4 r;
        r.x = fmaxf((a.x + s0.x) * di + b.x, 0.f);
        r.y = fmaxf((a.y + s0.y) * di + b.y, 0.f);
        r.z = fmaxf((a.z + s0.z) * di + b.z, 0.f);
        r.w = fmaxf((a.w + s0.w) * di + b.w, 0.f);
        if (valid) h[q] = r;
        float4 wr = __ldg(&((const float4*)wroot)[q]);
        float4 wl = __ldg(&((const float4*)wrel)[q]);
        sr += r.x * wr.x + r.y * wr.y + r.z * wr.z + r.w * wr.w;
        st += r.x * wl.x + r.y * wl.y + r.z * wl.z + r.w * wl.w;
    }
    sr += __shfl_xor_sync(0xFFFFFFFFu, sr, 1);
    st += __shfl_xor_sync(0xFFFFFFFFu, st, 1);
    if (valid && half == 0) {
        d_score[i] = sr + __ldg(&pb[0]);
        d_t[i] = st;
    }
}

__global__ void k_scats1(const int* __restrict__ src, const int* __restrict__ dst) {
    int e = blockIdx.x * blockDim.x + threadIdx.x;
    if (e < Ee) atomicAdd(&d_score[dst[e]], __ldg(&d_t[src[e]]));
}

// ---------------- grid barrier + hist scan helpers -----------------------------
__device__ __forceinline__ void gbar(unsigned* bar, unsigned target) {
    __threadfence();
    __syncthreads();
    if (threadIdx.x == 0) {
        atomicAdd(bar, 1u);
        while (*((volatile unsigned*)bar) < target) {}
    }
    __syncthreads();
    __threadfence();
}

__device__ __forceinline__ int scan_hist(const unsigned* gh, int nb, int& rem,
                                         unsigned* sh, volatile int* s_io) {
    for (int b = threadIdx.x; b < nb; b += 256) sh[b] = gh[b];
    __syncthreads();
    __shared__ unsigned part[256];
    int seg = nb >> 8;
    int base = threadIdx.x * seg;
    unsigned s = 0;
    for (int v = 0; v < seg; v++) s += sh[base + v];
    part[threadIdx.x] = s;
    __syncthreads();
    if (threadIdx.x == 0) {
        unsigned cum = 0;
        int t;
        for (t = 255; t >= 0; t--) {
            if (cum + part[t] >= (unsigned)rem) break;
            cum += part[t];
        }
        s_io[0] = t;
        s_io[1] = (int)cum;
    }
    __syncthreads();
    if ((int)threadIdx.x == s_io[0]) {
        int bb = s_io[0] * seg;
        unsigned cum = (unsigned)s_io[1];
        for (int v = seg - 1; v >= 0; v--) {
            unsigned c = sh[bb + v];
            cum += c;
            if (cum >= (unsigned)rem) {
                s_io[2] = bb + v;
                s_io[3] = rem - (int)(cum - c);
                break;
            }
        }
    }
    __syncthreads();
    int digit = s_io[2];
    rem = s_io[3];
    __syncthreads();
    return digit;
}

// ---------------- topk1: 4 passes + select (warp-aggregated reservation) -------
__global__ void __launch_bounds__(256, 1) k_topk1() {
    __shared__ unsigned sh[8192];
    __shared__ int s_io[4];
    const int shifts[4] = {36, 23, 10, 0};
    const int ws[4] = {13, 13, 13, 10};
    unsigned long long prefix = 0;
    int rem = Kk1;
#pragma unroll
    for (int p = 0; p < 4; p++) {
        int w = ws[p], shift = shifts[p], nb = 1 << w;
        unsigned mask = (unsigned)(nb - 1);
        for (int b = threadIdx.x; b < nb; b += 256) sh[b] = 0;
        __syncthreads();
        for (int i = blockIdx.x * 256 + threadIdx.x; i < Nn; i += G1 * 256) {
            unsigned long long key;
            if (p == 0) {
                key = ((unsigned long long)f2u(d_score[i]) << 17) |
                      (unsigned long long)(131071u - (unsigned)i);
                d_key[i] = key;
            } else key = d_key[i];
            if (p == 0 || (key >> (shift + w)) == prefix)
                atomicAdd(&sh[(unsigned)(key >> shift) & mask], 1u);
        }
        __syncthreads();
        for (int b = threadIdx.x; b < nb; b += 256)
            if (sh[b]) atomicAdd(&HIST(p)[b], sh[b]);
        gbar(&D_STATE[0], (unsigned)(p + 1) * G1);
        int digit = scan_hist(HIST(p), nb, rem, sh, s_io);
        prefix = (prefix << w) | (unsigned long long)digit;
    }
    int lane = threadIdx.x & 31;
    for (int i = blockIdx.x * 256 + threadIdx.x; i - threadIdx.x < Nn; i += G1 * 256) {
        bool sel = (i < Nn) && (d_key[i] >= prefix);
        unsigned m = __ballot_sync(0xFFFFFFFFu, sel);
        if (!m) continue;
        int leader = __ffs(m) - 1;
        int base = 0;
        if (lane == leader) base = atomicAdd((int*)&D_STATE[2], __popc(m));
        base = __shfl_sync(0xFFFFFFFFu, base, leader);
        if (sel) {
            int p = base + __popc(m & ((1u << lane) - 1u));
            d_perm[p] = i;
            atomicOr(&D_SELBIT[i >> 5], 1u << (i & 31));
            d_deg2[i] = 0;
            float th = tanhf(d_score[i]);
            const float4* h = (const float4*)&d_h[i * Hh];
            float4* o = (float4*)&d_x1[p * Hh];
#pragma unroll
            for (int q = 0; q < 4; q++) {
                float4 v = h[q];
                v.x *= th; v.y *= th; v.z *= th; v.w *= th;
                o[q] = v;
            }
        }
    }
}

__device__ __forceinline__ bool selbit(int i) {
    return (__ldg(&D_SELBIT[i >> 5]) >> (i & 31)) & 1u;
}

// ---------------- deg2 + edge compaction (block-aggregated reservation) --------
__global__ void k_deg2c(const int* __restrict__ src, const int* __restrict__ dst) {
    __shared__ int blk_cnt;
    __shared__ int blk_base;
    __shared__ int woff[8];
    int e = blockIdx.x * blockDim.x + threadIdx.x;
    int lane = threadIdx.x & 31, wid = threadIdx.x >> 5;
    if (threadIdx.x == 0) blk_cnt = 0;
    __syncthreads();
    int s = 0, d = 0;
    bool v = false;
    if (e < Ee) {
        s = src[e]; d = dst[e];
        v = selbit(s) && selbit(d);
    }
    unsigned m = __ballot_sync(0xFFFFFFFFu, v);
    if (v) atomicAdd(&d_deg2[d], 1);
    int wcnt = __popc(m);
    if (lane == 0 && wcnt) woff[wid] = atomicAdd(&blk_cnt, wcnt);
    __syncthreads();
    if (threadIdx.x == 0 && blk_cnt)
        blk_base = atomicAdd((int*)&D_STATE[3], blk_cnt);
    __syncthreads();
    if (v) {
        int pos = blk_base + woff[wid] + __popc(m & ((1u << lane) - 1u));
        d_eplist[pos] = ((unsigned long long)d << 32) | (unsigned)s;
    }
}

// ---------------- conv2: dinv2 + g0 = x1@W2 + self-loop init -------------------
__global__ void k_conv2(const float* __restrict__ W2, const float* __restrict__ b2) {
    int p = blockIdx.x * blockDim.x + threadIdx.x;
    if (p >= Kk1) return;
    int i = d_perm[p];
    float di = rsqrtf((float)d_deg2[i] + 1.0f);
    d_dinv2[i] = di;
    float s = di * di;
    float xr[Hh];
    const float4* xv = (const float4*)&d_x1[p * Hh];
#pragma unroll
    for (int q = 0; q < 4; q++) {
        float4 v = xv[q];
        xr[q*4] = v.x; xr[q*4+1] = v.y; xr[q*4+2] = v.z; xr[q*4+3] = v.w;
    }
    float* g = &d_g0[i * 16];
    float* h2 = &d_h2[i * 16];
#pragma unroll
    for (int j = 0; j < Cc; j++) {
        float a = 0.f;
#pragma unroll
        for (int f = 0; f < Hh; f++) a += xr[f] * __ldg(&W2[f * Cc + j]);
        g[j] = a;
        h2[j] = a * s + __ldg(&b2[j]);
    }
#pragma unroll
    for (int j = Cc; j < 16; j++) { g[j] = 0.f; h2[j] = 0.f; }
}

__global__ void k_scat2() {
    int ecnt = (int)D_STATE[3];
    for (int k = blockIdx.x * blockDim.x + threadIdx.x; k < ecnt;
         k += gridDim.x * blockDim.x) {
        unsigned long long pk = d_eplist[k];
        int s = (int)(pk & 0xFFFFFFFFu), d = (int)(pk >> 32);
        float nrm = __ldg(&d_dinv2[s]) * __ldg(&d_dinv2[d]);
        const float4* g = (const float4*)&d_g0[s * 16];
        float* a = &d_h2[d * 16];
#pragma unroll
        for (int q = 0; q < 3; q++) {
            float4 v = g[q];
            v.x *= nrm; v.y *= nrm; v.z *= nrm; v.w *= nrm;
            red_v4(a + q * 4, v);
        }
    }
}

__global__ void k_prep2(const float* __restrict__ wroot, const float* __restrict__ wrel,
                        const float* __restrict__ pb) {
    int p = blockIdx.x * blockDim.x + threadIdx.x;
    if (p >= Kk1) return;
    int i = d_perm[p];
    float sr = 0.f, st = 0.f;
#pragma unroll
    for (int j = 0; j < Cc; j++) {
        float v = d_h2[i * 16 + j];
        sr += v * __ldg(&wroot[j]);
        st += v * __ldg(&wrel[j]);
    }
    d_score2[i] = sr + __ldg(&pb[0]);
    d_t2[i] = st;
}

__global__ void k_scats2() {
    int ecnt = (int)D_STATE[3];
    for (int k = blockIdx.x * blockDim.x + threadIdx.x; k < ecnt;
         k += gridDim.x * blockDim.x) {
        unsigned long long pk = d_eplist[k];
        int s = (int)(pk & 0xFFFFFFFFu), d = (int)(pk >> 32);
        atomicAdd(&d_score2[d], __ldg(&d_t2[s]));
    }
}

// ---------------- topk2: 4 passes + select + mean + log_softmax ----------------
__global__ void __launch_bounds__(256, 1) k_topk2(float* __restrict__ out) {
    __shared__ unsigned sh[8192];
    __shared__ int s_io[4];
    const int shifts[4] = {34, 21, 8, 0};
    const int ws[4] = {13, 13, 13, 8};
    unsigned long long prefix = 0;
    int rem = Kk2;
#pragma unroll
    for (int p = 0; p < 4; p++) {
        int w = ws[p], shift = shifts[p], nb = 1 << w;
        unsigned mask = (unsigned)(nb - 1);
        for (int b = threadIdx.x; b < nb; b += 256) sh[b] = 0;
        __syncthreads();
        for (int i = blockIdx.x * 256 + threadIdx.x; i < Kk1; i += G2 * 256) {
            unsigned long long key;
            if (p == 0) {
                float sc = __ldg(&d_score2[d_perm[i]]);
                key = ((unsigned long long)f2u(sc) << 15) |
                      (unsigned long long)(32767u - (unsigned)i);
                d_key[i] = key;
            } else key = d_key[i];
            if (p == 0 || (key >> (shift + w)) == prefix)
                atomicAdd(&sh[(unsigned)(key >> shift) & mask], 1u);
        }
        __syncthreads();
        for (int b = threadIdx.x; b < nb; b += 256)
            if (sh[b]) atomicAdd(&HIST(4 + p)[b], sh[b]);
        gbar(&D_STATE[1], (unsigned)(p + 1) * G2);
        int digit = scan_hist(HIST(4 + p), nb, rem, sh, s_io);
        prefix = (prefix << w) | (unsigned long long)digit;
    }
    float acc[Cc];
#pragma unroll
    for (int j = 0; j < Cc; j++) acc[j] = 0.f;
    for (int i = blockIdx.x * 256 + threadIdx.x; i < Kk1; i += G2 * 256) {
        if (d_key[i] >= prefix) {
            int n = d_perm[i];
            float th = tanhf(d_score2[n]);
#pragma unroll
            for (int j = 0; j < Cc; j++) acc[j] += d_h2[n * 16 + j] * th;
        }
    }
#pragma unroll
    for (int o = 16; o; o >>= 1)
#pragma unroll
        for (int j = 0; j < Cc; j++) acc[j] += __shfl_xor_sync(0xFFFFFFFFu, acc[j], o);
    if ((threadIdx.x & 31) == 0)
#pragma unroll
        for (int j = 0; j < Cc; j++) atomicAdd(&D_ACC[j], acc[j]);
    __threadfence();
    __syncthreads();
    if (threadIdx.x == 0) {
        if (atomicAdd(&D_STATE[4], 1u) == (unsigned)G2 - 1u) {
            float m[Cc], mx = -1e30f;
#pragma unroll
            for (int j = 0; j < Cc; j++) {
                m[j] = D_ACC[j] / (float)Kk2;
                mx = fmaxf(mx, m[j]);
            }
            float lse = 0.f;
#pragma unroll
            for (int j = 0; j < Cc; j++) lse += expf(m[j] - mx);
            lse = logf(lse);
#pragma unroll
            for (int j = 0; j < Cc; j++) out[j] = m[j] - mx - lse;
        }
    }
}

// ---------------- launch --------------------------------------------------------
extern "C" void kernel_launch(void* const* d_in, const int* in_sizes, int n_in,
                              void* d_out, int out_size) {
    const float* x = (const float*)d_in[0];
    const int* esrc = (const int*)d_in[1];
    const int* edst = (const int*)d_in[2];
    const float* W1 = (const float*)d_in[3];
    const float* b1 = (const float*)d_in[4];
    const float* p1wr = (const float*)d_in[5];
    const float* p1wl = (const float*)d_in[6];
    const float* p1b = (const float*)d_in[7];
    const float* W2 = (const float*)d_in[8];
    const float* b2 = (const float*)d_in[9];
    const float* p2wr = (const float*)d_in[10];
    const float* p2wl = (const float*)d_in[11];
    const float* p2b = (const float*)d_in[12];
    float* out = (float*)d_out;

    void *p_h, *p_deg, *p_blob;
    cudaGetSymbolAddress(&p_h, d_h);
    cudaGetSymbolAddress(&p_deg, d_deg);
    cudaGetSymbolAddress(&p_blob, d_blob);
    cudaMemsetAsync(p_h, 0, Nn * Hh * sizeof(float));
    cudaMemsetAsync(p_deg, 0, Nn * sizeof(int));
    cudaMemsetAsync(p_blob, 0, 68696 * sizeof(unsigned));

    const int T = 256;
    k_front<<<MM1_BLOCKS + DEG_BLOCKS, T>>>(x, W1, edst);
    k_dinv<<<(2 * Nn + T - 1) / T, T>>>();
    k_scat1<<<(Ee * 4) / T, T>>>(esrc, edst);
    k_prep1<<<(2 * Nn + T - 1) / T, T>>>(b1, p1wr, p1wl, p1b);
    k_scats1<<<(Ee + T - 1) / T, T>>>(esrc, edst);
    k_topk1<<<G1, 256>>>();
    k_deg2c<<<(Ee + T - 1) / T, T>>>(esrc, edst);
    k_conv2<<<(Kk1 + T - 1) / T, T>>>(W2, b2);
    k_scat2<<<416, T>>>();
    k_prep2<<<(Kk1 + T - 1) / T, T>>>(p2wr, p2wl, p2b);
    k_scats2<<<416, T>>>();
    k_topk2<<<G2, 256>>>(out);
}

// round 15
// speedup vs baseline: 1.1259x; 1.1259x over previous
#include <cuda_runtime.h>
#include <math.h>

#define Nn 100000
#define Ee 3200000
#define Ff 128
#define Hh 16
#define Cc 10
#define Kk1 25000
#define Kk2 6250
#define G1 64     // topk1 persistent grid
#define G2 32     // topk2 persistent grid

// ---------------- scratch ------------------------------------------------------
__device__ __align__(16) float d_h0[Nn * Hh];   // x@W1, then scaled by dinv
__device__ __align__(16) float d_h[Nn * Hh];    // conv1 edge accumulator (memset 0)
__device__ float d_dinv[Nn];
__device__ int d_deg[Nn];                        // memset 0
__device__ float d_t[Nn];
__device__ float d_score[Nn];
__device__ unsigned long long d_key[Nn];
__device__ int d_perm[Kk1];
__device__ int d_deg2[Nn];
__device__ float d_dinv2[Nn];
__device__ __align__(16) float d_x1[Kk1 * Hh];
__device__ __align__(16) float d_g0[Nn * 16];
__device__ __align__(16) float d_h2[Nn * 16];
__device__ float d_t2[Nn];
__device__ float d_score2[Nn];
__device__ unsigned long long d_eplist[Ee];

// one zeroed blob: hist[8][8192] | selbit[3136] | state[8] | acc[10]
__device__ __align__(16) unsigned d_blob[68696];
#define HIST(p) (d_blob + (p) * 8192)
#define D_SELBIT (d_blob + 65536)
#define D_STATE (d_blob + 68672)   // 0:bar1 1:bar2 2:permcnt 3:ecnt 4:tick
#define D_ACC ((float*)(d_blob + 68680))

__device__ __forceinline__ void red_v4(float* p, float4 v) {
    asm volatile("red.global.add.v4.f32 [%0], {%1,%2,%3,%4};"
                 :: "l"(p), "f"(v.x), "f"(v.y), "f"(v.z), "f"(v.w) : "memory");
}
__device__ __forceinline__ unsigned f2u(float f) {
    unsigned u = __float_as_uint(f);
    return (u & 0x80000000u) ? ~u : (u | 0x80000000u);
}

// ---------------- fused: h0 = x @ W1 (grid-stride warps)  ||  deg count --------
#define MM1_BLOCKS 1536
#define DEG_BLOCKS 1024
__global__ void k_front(const float* __restrict__ x, const float* __restrict__ W1,
                        const int* __restrict__ dst) {
    if (blockIdx.x < MM1_BLOCKS) {
        __shared__ float Ws[Ff * Hh];
        for (int i = threadIdx.x; i < Ff * Hh; i += blockDim.x) Ws[i] = W1[i];
        __syncthreads();
        int lane = threadIdx.x & 31;
        for (int node = blockIdx.x * 8 + (threadIdx.x >> 5); node < Nn;
             node += MM1_BLOCKS * 8) {
            const float* xr = x + (size_t)node * Ff;
            float acc[Hh];
#pragma unroll
            for (int j = 0; j < Hh; j++) acc[j] = 0.f;
#pragma unroll
            for (int c = 0; c < 4; c++) {
                int f = c * 32 + lane;
                float xv = xr[f];
                const float* wr = Ws + f * Hh;
#pragma unroll
                for (int j = 0; j < Hh; j++) acc[j] += xv * wr[j];
            }
            // column-folding reduction: 17 SHFL instead of 80.
            {
                bool hi = (lane & 16) != 0;
#pragma unroll
                for (int j = 0; j < 8; j++) {
                    float sent = hi ? acc[j] : acc[j + 8];
                    float recv = __shfl_xor_sync(0xFFFFFFFFu, sent, 16);
                    acc[j] = (hi ? acc[j + 8] : acc[j]) + recv;
                }
            }
            {
                bool hi = (lane & 8) != 0;
#pragma unroll
                for (int j = 0; j < 4; j++) {
                    float sent = hi ? acc[j] : acc[j + 4];
                    float recv = __shfl_xor_sync(0xFFFFFFFFu, sent, 8);
                    acc[j] = (hi ? acc[j + 4] : acc[j]) + recv;
                }
            }
            {
                bool hi = (lane & 4) != 0;
#pragma unroll
                for (int j = 0; j < 2; j++) {
                    float sent = hi ? acc[j] : acc[j + 2];
                    float recv = __shfl_xor_sync(0xFFFFFFFFu, sent, 4);
                    acc[j] = (hi ? acc[j + 2] : acc[j]) + recv;
                }
            }
            {
                bool hi = (lane & 2) != 0;
                float sent = hi ? acc[0] : acc[1];
                float recv = __shfl_xor_sync(0xFFFFFFFFu, sent, 2);
                acc[0] = (hi ? acc[1] : acc[0]) + recv;
            }
            acc[0] += __shfl_xor_sync(0xFFFFFFFFu, acc[0], 1);
            float colv = __shfl_sync(0xFFFFFFFFu, acc[0], (lane << 1) & 31);
            if (lane < Hh) d_h0[(size_t)node * Hh + lane] = colv;
        }
    } else {
        for (int e = (blockIdx.x - MM1_BLOCKS) * 256 + threadIdx.x; e < Ee;
             e += DEG_BLOCKS * 256)
            atomicAdd(&d_deg[dst[e]], 1);
    }
}

// dinv + pre-scale h0 (2 threads per node)
__global__ void k_dinv() {
    int gid = blockIdx.x * blockDim.x + threadIdx.x;
    int i = gid >> 1, half = gid & 1;
    bool valid = i < Nn;
    if (!valid) i = Nn - 1;
    float di = rsqrtf((float)d_deg[i] + 1.0f);
    if (valid && half == 0) d_dinv[i] = di;
    float4* h0 = (float4*)&d_h0[i * Hh];
#pragma unroll
    for (int qq = 0; qq < 2; qq++) {
        int q = half * 2 + qq;
        float4 v = h0[q];
        v.x *= di; v.y *= di; v.z *= di; v.w *= di;
        if (valid) h0[q] = v;
    }
}

__global__ void k_scat1(const int* __restrict__ src, const int* __restrict__ dst) {
    int t = blockIdx.x * blockDim.x + threadIdx.x;
    int e = t >> 2, q = t & 3;
    int s = src[e], d = dst[e];
    float4 v = *(const float4*)&d_h0[s * Hh + q * 4];
    red_v4(&d_h[d * Hh + q * 4], v);
}

// finalize conv1 (2 threads per node)
__global__ void k_prep1(const float* __restrict__ b1, const float* __restrict__ wroot,
                        const float* __restrict__ wrel, const float* __restrict__ pb) {
    int gid = blockIdx.x * blockDim.x + threadIdx.x;
    int i = gid >> 1, half = gid & 1;
    bool valid = i < Nn;
    if (!valid) i = Nn - 1;
    float di = d_dinv[i];
    float4* h = (float4*)&d_h[i * Hh];
    const float4* h0 = (const float4*)&d_h0[i * Hh];
    float sr = 0.f, st = 0.f;
#pragma unroll
    for (int qq = 0; qq < 2; qq++) {
        int q = half * 2 + qq;
        float4 a = h[q], s0 = h0[q];
        float4 b = __ldg(&((const float4*)b1)[q]);
        float4 r;
        r.x = fmaxf((a.x + s0.x) * di + b.x, 0.f);
        r.y = fmaxf((a.y + s0.y) * di + b.y, 0.f);
        r.z = fmaxf((a.z + s0.z) * di + b.z, 0.f);
        r.w = fmaxf((a.w + s0.w) * di + b.w, 0.f);
        if (valid) h[q] = r;
        float4 wr = __ldg(&((const float4*)wroot)[q]);
        float4 wl = __ldg(&((const float4*)wrel)[q]);
        sr += r.x * wr.x + r.y * wr.y + r.z * wr.z + r.w * wr.w;
        st += r.x * wl.x + r.y * wl.y + r.z * wl.z + r.w * wl.w;
    }
    sr += __shfl_xor_sync(0xFFFFFFFFu, sr, 1);
    st += __shfl_xor_sync(0xFFFFFFFFu, st, 1);
    if (valid && half == 0) {
        d_score[i] = sr + __ldg(&pb[0]);
        d_t[i] = st;
    }
}

__global__ void k_scats1(const int* __restrict__ src, const int* __restrict__ dst) {
    int e = blockIdx.x * blockDim.x + threadIdx.x;
    if (e < Ee) atomicAdd(&d_score[dst[e]], __ldg(&d_t[src[e]]));
}

// ---------------- grid barrier + hist scan helpers -----------------------------
__device__ __forceinline__ void gbar(unsigned* bar, unsigned target) {
    __threadfence();
    __syncthreads();
    if (threadIdx.x == 0) {
        atomicAdd(bar, 1u);
        while (*((volatile unsigned*)bar) < target) {}
    }
    __syncthreads();
    __threadfence();
}

__device__ __forceinline__ int scan_hist(const unsigned* gh, int nb, int& rem,
                                         unsigned* sh, volatile int* s_io) {
    for (int b = threadIdx.x; b < nb; b += 256) sh[b] = gh[b];
    __syncthreads();
    __shared__ unsigned part[256];
    int seg = nb >> 8;
    int base = threadIdx.x * seg;
    unsigned s = 0;
    for (int v = 0; v < seg; v++) s += sh[base + v];
    part[threadIdx.x] = s;
    __syncthreads();
    if (threadIdx.x == 0) {
        unsigned cum = 0;
        int t;
        for (t = 255; t >= 0; t--) {
            if (cum + part[t] >= (unsigned)rem) break;
            cum += part[t];
        }
        s_io[0] = t;
        s_io[1] = (int)cum;
    }
    __syncthreads();
    if ((int)threadIdx.x == s_io[0]) {
        int bb = s_io[0] * seg;
        unsigned cum = (unsigned)s_io[1];
        for (int v = seg - 1; v >= 0; v--) {
            unsigned c = sh[bb + v];
            cum += c;
            if (cum >= (unsigned)rem) {
                s_io[2] = bb + v;
                s_io[3] = rem - (int)(cum - c);
                break;
            }
        }
    }
    __syncthreads();
    int digit = s_io[2];
    rem = s_io[3];
    __syncthreads();
    return digit;
}

// ---------------- topk1: 4 passes + select (warp-aggregated reservation) -------
__global__ void __launch_bounds__(256, 1) k_topk1() {
    __shared__ unsigned sh[8192];
    __shared__ int s_io[4];
    const int shifts[4] = {36, 23, 10, 0};
    const int ws[4] = {13, 13, 13, 10};
    unsigned long long prefix = 0;
    int rem = Kk1;
#pragma unroll
    for (int p = 0; p < 4; p++) {
        int w = ws[p], shift = shifts[p], nb = 1 << w;
        unsigned mask = (unsigned)(nb - 1);
        for (int b = threadIdx.x; b < nb; b += 256) sh[b] = 0;
        __syncthreads();
        for (int i = blockIdx.x * 256 + threadIdx.x; i < Nn; i += G1 * 256) {
            unsigned long long key;
            if (p == 0) {
                key = ((unsigned long long)f2u(d_score[i]) << 17) |
                      (unsigned long long)(131071u - (unsigned)i);
                d_key[i] = key;
            } else key = d_key[i];
            if (p == 0 || (key >> (shift + w)) == prefix)
                atomicAdd(&sh[(unsigned)(key >> shift) & mask], 1u);
        }
        __syncthreads();
        for (int b = threadIdx.x; b < nb; b += 256)
            if (sh[b]) atomicAdd(&HIST(p)[b], sh[b]);
        gbar(&D_STATE[0], (unsigned)(p + 1) * G1);
        int digit = scan_hist(HIST(p), nb, rem, sh, s_io);
        prefix = (prefix << w) | (unsigned long long)digit;
    }
    int lane = threadIdx.x & 31;
    for (int i = blockIdx.x * 256 + threadIdx.x; i - threadIdx.x < Nn; i += G1 * 256) {
        bool sel = (i < Nn) && (d_key[i] >= prefix);
        unsigned m = __ballot_sync(0xFFFFFFFFu, sel);
        if (!m) continue;
        int leader = __ffs(m) - 1;
        int base = 0;
        if (lane == leader) base = atomicAdd((int*)&D_STATE[2], __popc(m));
        base = __shfl_sync(0xFFFFFFFFu, base, leader);
        if (sel) {
            int p = base + __popc(m & ((1u << lane) - 1u));
            d_perm[p] = i;
            atomicOr(&D_SELBIT[i >> 5], 1u << (i & 31));
            d_deg2[i] = 0;
            float th = tanhf(d_score[i]);
            const float4* h = (const float4*)&d_h[i * Hh];
            float4* o = (float4*)&d_x1[p * Hh];
#pragma unroll
            for (int q = 0; q < 4; q++) {
                float4 v = h[q];
                v.x *= th; v.y *= th; v.z *= th; v.w *= th;
                o[q] = v;
            }
        }
    }
}

__device__ __forceinline__ bool selbit(int i) {
    return (__ldg(&D_SELBIT[i >> 5]) >> (i & 31)) & 1u;
}

// ---------------- deg2 + edge compaction (block-aggregated reservation) --------
__global__ void k_deg2c(const int* __restrict__ src, const int* __restrict__ dst) {
    __shared__ int blk_cnt;
    __shared__ int blk_base;
    __shared__ int woff[8];
    int e = blockIdx.x * blockDim.x + threadIdx.x;
    int lane = threadIdx.x & 31, wid = threadIdx.x >> 5;
    if (threadIdx.x == 0) blk_cnt = 0;
    __syncthreads();
    int s = 0, d = 0;
    bool v = false;
    if (e < Ee) {
        s = src[e]; d = dst[e];
        v = selbit(s) && selbit(d);
    }
    unsigned m = __ballot_sync(0xFFFFFFFFu, v);
    if (v) atomicAdd(&d_deg2[d], 1);
    int wcnt = __popc(m);
    if (lane == 0 && wcnt) woff[wid] = atomicAdd(&blk_cnt, wcnt);
    __syncthreads();
    if (threadIdx.x == 0 && blk_cnt)
        blk_base = atomicAdd((int*)&D_STATE[3], blk_cnt);
    __syncthreads();
    if (v) {
        int pos = blk_base + woff[wid] + __popc(m & ((1u << lane) - 1u));
        d_eplist[pos] = ((unsigned long long)d << 32) | (unsigned)s;
    }
}

// ---------------- conv2: dinv2 + g0 = x1@W2 + self-loop init -------------------
__global__ void k_conv2(const float* __restrict__ W2, const float* __restrict__ b2) {
    int p = blockIdx.x * blockDim.x + threadIdx.x;
    if (p >= Kk1) return;
    int i = d_perm[p];
    float di = rsqrtf((float)d_deg2[i] + 1.0f);
    d_dinv2[i] = di;
    float s = di * di;
    float xr[Hh];
    const float4* xv = (const float4*)&d_x1[p * Hh];
#pragma unroll
    for (int q = 0; q < 4; q++) {
        float4 v = xv[q];
        xr[q*4] = v.x; xr[q*4+1] = v.y; xr[q*4+2] = v.z; xr[q*4+3] = v.w;
    }
    float* g = &d_g0[i * 16];
    float* h2 = &d_h2[i * 16];
#pragma unroll
    for (int j = 0; j < Cc; j++) {
        float a = 0.f;
#pragma unroll
        for (int f = 0; f < Hh; f++) a += xr[f] * __ldg(&W2[f * Cc + j]);
        g[j] = a;
        h2[j] = a * s + __ldg(&b2[j]);
    }
#pragma unroll
    for (int j = Cc; j < 16; j++) { g[j] = 0.f; h2[j] = 0.f; }
}

__global__ void k_scat2() {
    int ecnt = (int)D_STATE[3];
    for (int k = blockIdx.x * blockDim.x + threadIdx.x; k < ecnt;
         k += gridDim.x * blockDim.x) {
        unsigned long long pk = d_eplist[k];
        int s = (int)(pk & 0xFFFFFFFFu), d = (int)(pk >> 32);
        float nrm = __ldg(&d_dinv2[s]) * __ldg(&d_dinv2[d]);
        const float4* g = (const float4*)&d_g0[s * 16];
        float* a = &d_h2[d * 16];
#pragma unroll
        for (int q = 0; q < 3; q++) {
            float4 v = g[q];
            v.x *= nrm; v.y *= nrm; v.z *= nrm; v.w *= nrm;
            red_v4(a + q * 4, v);
        }
    }
}

__global__ void k_prep2(const float* __restrict__ wroot, const float* __restrict__ wrel,
                        const float* __restrict__ pb) {
    int p = blockIdx.x * blockDim.x + threadIdx.x;
    if (p >= Kk1) return;
    int i = d_perm[p];
    float sr = 0.f, st = 0.f;
#pragma unroll
    for (int j = 0; j < Cc; j++) {
        float v = d_h2[i * 16 + j];
        sr += v * __ldg(&wroot[j]);
        st += v * __ldg(&wrel[j]);
    }
    d_score2[i] = sr + __ldg(&pb[0]);
    d_t2[i] = st;
}

__global__ void k_scats2() {
    int ecnt = (int)D_STATE[3];
    for (int k = blockIdx.x * blockDim.x + threadIdx.x; k < ecnt;
         k += gridDim.x * blockDim.x) {
        unsigned long long pk = d_eplist[k];
        int s = (int)(pk & 0xFFFFFFFFu), d = (int)(pk >> 32);
        atomicAdd(&d_score2[d], __ldg(&d_t2[s]));
    }
}

// ---------------- topk2: 4 passes + select + mean + log_softmax ----------------
__global__ void __launch_bounds__(256, 1) k_topk2(float* __restrict__ out) {
    __shared__ unsigned sh[8192];
    __shared__ int s_io[4];
    const int shifts[4] = {34, 21, 8, 0};
    const int ws[4] = {13, 13, 13, 8};
    unsigned long long prefix = 0;
    int rem = Kk2;
#pragma unroll
    for (int p = 0; p < 4; p++) {
        int w = ws[p], shift = shifts[p], nb = 1 << w;
        unsigned mask = (unsigned)(nb - 1);
        for (int b = threadIdx.x; b < nb; b += 256) sh[b] = 0;
        __syncthreads();
        for (int i = blockIdx.x * 256 + threadIdx.x; i < Kk1; i += G2 * 256) {
            unsigned long long key;
            if (p == 0) {
                float sc = __ldg(&d_score2[d_perm[i]]);
                key = ((unsigned long long)f2u(sc) << 15) |
                      (unsigned long long)(32767u - (unsigned)i);
                d_key[i] = key;
            } else key = d_key[i];
            if (p == 0 || (key >> (shift + w)) == prefix)
                atomicAdd(&sh[(unsigned)(key >> shift) & mask], 1u);
        }
        __syncthreads();
        for (int b = threadIdx.x; b < nb; b += 256)
            if (sh[b]) atomicAdd(&HIST(4 + p)[b], sh[b]);
        gbar(&D_STATE[1], (unsigned)(p + 1) * G2);
        int digit = scan_hist(HIST(4 + p), nb, rem, sh, s_io);
        prefix = (prefix << w) | (unsigned long long)digit;
    }
    float acc[Cc];
#pragma unroll
    for (int j = 0; j < Cc; j++) acc[j] = 0.f;
    for (int i = blockIdx.x * 256 + threadIdx.x; i < Kk1; i += G2 * 256) {
        if (d_key[i] >= prefix) {
            int n = d_perm[i];
            float th = tanhf(d_score2[n]);
#pragma unroll
            for (int j = 0; j < Cc; j++) acc[j] += d_h2[n * 16 + j] * th;
        }
    }
#pragma unroll
    for (int o = 16; o; o >>= 1)
#pragma unroll
        for (int j = 0; j < Cc; j++) acc[j] += __shfl_xor_sync(0xFFFFFFFFu, acc[j], o);
    if ((threadIdx.x & 31) == 0)
#pragma unroll
        for (int j = 0; j < Cc; j++) atomicAdd(&D_ACC[j], acc[j]);
    __threadfence();
    __syncthreads();
    if (threadIdx.x == 0) {
        if (atomicAdd(&D_STATE[4], 1u) == (unsigned)G2 - 1u) {
            float m[Cc], mx = -1e30f;
#pragma unroll
            for (int j = 0; j < Cc; j++) {
                m[j] = D_ACC[j] / (float)Kk2;
                mx = fmaxf(mx, m[j]);
            }
            float lse = 0.f;
#pragma unroll
            for (int j = 0; j < Cc; j++) lse += expf(m[j] - mx);
            lse = logf(lse);
#pragma unroll
            for (int j = 0; j < Cc; j++) out[j] = m[j] - mx - lse;
        }
    }
}

// ---------------- launch --------------------------------------------------------
extern "C" void kernel_launch(void* const* d_in, const int* in_sizes, int n_in,
                              void* d_out, int out_size) {
    const float* x = (const float*)d_in[0];
    const int* esrc = (const int*)d_in[1];
    const int* edst = (const int*)d_in[2];
    const float* W1 = (const float*)d_in[3];
    const float* b1 = (const float*)d_in[4];
    const float* p1wr = (const float*)d_in[5];
    const float* p1wl = (const float*)d_in[6];
    const float* p1b = (const float*)d_in[7];
    const float* W2 = (const float*)d_in[8];
    const float* b2 = (const float*)d_in[9];
    const float* p2wr = (const float*)d_in[10];
    const float* p2wl = (const float*)d_in[11];
    const float* p2b = (const float*)d_in[12];
    float* out = (float*)d_out;

    void *p_h, *p_deg, *p_blob;
    cudaGetSymbolAddress(&p_h, d_h);
    cudaGetSymbolAddress(&p_deg, d_deg);
    cudaGetSymbolAddress(&p_blob, d_blob);
    cudaMemsetAsync(p_h, 0, Nn * Hh * sizeof(float));
    cudaMemsetAsync(p_deg, 0, Nn * sizeof(int));
    cudaMemsetAsync(p_blob, 0, 68696 * sizeof(unsigned));

    const int T = 256;
    k_front<<<MM1_BLOCKS + DEG_BLOCKS, T>>>(x, W1, edst);
    k_dinv<<<(2 * Nn + T - 1) / T, T>>>();
    k_scat1<<<(Ee * 4) / T, T>>>(esrc, edst);
    k_prep1<<<(2 * Nn + T - 1) / T, T>>>(b1, p1wr, p1wl, p1b);
    k_scats1<<<(Ee + T - 1) / T, T>>>(esrc, edst);
    k_topk1<<<G1, 256>>>();
    k_deg2c<<<(Ee + T - 1) / T, T>>>(esrc, edst);
    k_conv2<<<(Kk1 + T - 1) / T, T>>>(W2, b2);
    k_scat2<<<416, T>>>();
    k_prep2<<<(Kk1 + T - 1) / T, T>>>(p2wr, p2wl, p2b);
    k_scats2<<<416, T>>>();
    k_topk2<<<G2, 256>>>(out);
}

// round 16
// speedup vs baseline: 1.3286x; 1.1801x over previous
#include <cuda_runtime.h>
#include <math.h>

#define Nn 100000
#define Ee 3200000
#define Ff 128
#define Hh 16
#define Cc 10
#define Kk1 25000
#define Kk2 6250
#define G1 64     // topk1 persistent grid
#define G2 32     // topk2 persistent grid

// ---------------- scratch ------------------------------------------------------
__device__ __align__(16) float d_h0[Nn * Hh];   // x@W1, then scaled by dinv
__device__ __align__(16) float d_h[Nn * Hh];    // conv1 edge accumulator (memset 0)
__device__ float d_dinv[Nn];
__device__ int d_deg[Nn];                        // memset 0
__device__ float d_t[Nn];
__device__ float d_score[Nn];
__device__ unsigned d_key32[Nn];
__device__ int d_perm[Kk1];
__device__ int d_deg2[Nn];
__device__ float d_dinv2[Nn];
__device__ __align__(16) float d_x1[Kk1 * Hh];
__device__ __align__(16) float d_g0[Nn * 16];
__device__ __align__(16) float d_h2[Nn * 16];
__device__ float d_t2[Nn];
__device__ float d_score2[Nn];
__device__ unsigned long long d_eplist[Ee];
__device__ int d_tie[32768];

// one zeroed blob: hist[8][8192] | selbit[3136] | state[8] | acc[10]
__device__ __align__(16) unsigned d_blob[68696];
#define HIST(p) (d_blob + (p) * 8192)
#define D_SELBIT (d_blob + 65536)
#define D_STATE (d_blob + 68672)  // 0:bar1 1:bar2 2:permcnt 3:ecnt 4:- 5:tie1 6:tie2
#define D_ACC ((float*)(d_blob + 68680))

__device__ __forceinline__ void red_v4(float* p, float4 v) {
    asm volatile("red.global.add.v4.f32 [%0], {%1,%2,%3,%4};"
                 :: "l"(p), "f"(v.x), "f"(v.y), "f"(v.z), "f"(v.w) : "memory");
}
__device__ __forceinline__ unsigned f2u(float f) {
    unsigned u = __float_as_uint(f);
    return (u & 0x80000000u) ? ~u : (u | 0x80000000u);
}

// ---------------- fused: h0 = x @ W1 (grid-stride warps)  ||  deg count --------
#define MM1_BLOCKS 1536
#define DEG_BLOCKS 1024
__global__ void k_front(const float* __restrict__ x, const float* __restrict__ W1,
                        const int* __restrict__ dst) {
    if (blockIdx.x < MM1_BLOCKS) {
        __shared__ float Ws[Ff * Hh];
        for (int i = threadIdx.x; i < Ff * Hh; i += blockDim.x) Ws[i] = W1[i];
        __syncthreads();
        int lane = threadIdx.x & 31;
        for (int node = blockIdx.x * 8 + (threadIdx.x >> 5); node < Nn;
             node += MM1_BLOCKS * 8) {
            const float* xr = x + (size_t)node * Ff;
            float acc[Hh];
#pragma unroll
            for (int j = 0; j < Hh; j++) acc[j] = 0.f;
#pragma unroll
            for (int c = 0; c < 4; c++) {
                int f = c * 32 + lane;
                float xv = xr[f];
                const float* wr = Ws + f * Hh;
#pragma unroll
                for (int j = 0; j < Hh; j++) acc[j] += xv * wr[j];
            }
            // column-folding reduction: 17 SHFL instead of 80.
            {
                bool hi = (lane & 16) != 0;
#pragma unroll
                for (int j = 0; j < 8; j++) {
                    float sent = hi ? acc[j] : acc[j + 8];
                    float recv = __shfl_xor_sync(0xFFFFFFFFu, sent, 16);
                    acc[j] = (hi ? acc[j + 8] : acc[j]) + recv;
                }
            }
            {
                bool hi = (lane & 8) != 0;
#pragma unroll
                for (int j = 0; j < 4; j++) {
                    float sent = hi ? acc[j] : acc[j + 4];
                    float recv = __shfl_xor_sync(0xFFFFFFFFu, sent, 8);
                    acc[j] = (hi ? acc[j + 4] : acc[j]) + recv;
                }
            }
            {
                bool hi = (lane & 4) != 0;
#pragma unroll
                for (int j = 0; j < 2; j++) {
                    float sent = hi ? acc[j] : acc[j + 2];
                    float recv = __shfl_xor_sync(0xFFFFFFFFu, sent, 4);
                    acc[j] = (hi ? acc[j + 2] : acc[j]) + recv;
                }
            }
            {
                bool hi = (lane & 2) != 0;
                float sent = hi ? acc[0] : acc[1];
                float recv = __shfl_xor_sync(0xFFFFFFFFu, sent, 2);
                acc[0] = (hi ? acc[1] : acc[0]) + recv;
            }
            acc[0] += __shfl_xor_sync(0xFFFFFFFFu, acc[0], 1);
            float colv = __shfl_sync(0xFFFFFFFFu, acc[0], (lane << 1) & 31);
            if (lane < Hh) d_h0[(size_t)node * Hh + lane] = colv;
        }
    } else {
        for (int e = (blockIdx.x - MM1_BLOCKS) * 256 + threadIdx.x; e < Ee;
             e += DEG_BLOCKS * 256)
            atomicAdd(&d_deg[dst[e]], 1);
    }
}

// dinv + pre-scale h0 (2 threads per node)
__global__ void k_dinv() {
    int gid = blockIdx.x * blockDim.x + threadIdx.x;
    int i = gid >> 1, half = gid & 1;
    bool valid = i < Nn;
    if (!valid) i = Nn - 1;
    float di = rsqrtf((float)d_deg[i] + 1.0f);
    if (valid && half == 0) d_dinv[i] = di;
    float4* h0 = (float4*)&d_h0[i * Hh];
#pragma unroll
    for (int qq = 0; qq < 2; qq++) {
        int q = half * 2 + qq;
        float4 v = h0[q];
        v.x *= di; v.y *= di; v.z *= di; v.w *= di;
        if (valid) h0[q] = v;
    }
}

__global__ void k_scat1(const int* __restrict__ src, const int* __restrict__ dst) {
    int t = blockIdx.x * blockDim.x + threadIdx.x;
    int e = t >> 2, q = t & 3;
    int s = src[e], d = dst[e];
    float4 v = *(const float4*)&d_h0[s * Hh + q * 4];
    red_v4(&d_h[d * Hh + q * 4], v);
}

// finalize conv1 (2 threads per node)
__global__ void k_prep1(const float* __restrict__ b1, const float* __restrict__ wroot,
                        const float* __restrict__ wrel, const float* __restrict__ pb) {
    int gid = blockIdx.x * blockDim.x + threadIdx.x;
    int i = gid >> 1, half = gid & 1;
    bool valid = i < Nn;
    if (!valid) i = Nn - 1;
    float di = d_dinv[i];
    float4* h = (float4*)&d_h[i * Hh];
    const float4* h0 = (const float4*)&d_h0[i * Hh];
    float sr = 0.f, st = 0.f;
#pragma unroll
    for (int qq = 0; qq < 2; qq++) {
        int q = half * 2 + qq;
        float4 a = h[q], s0 = h0[q];
        float4 b = __ldg(&((const float4*)b1)[q]);
        float4 r;
        r.x = fmaxf((a.x + s0.x) * di + b.x, 0.f);
        r.y = fmaxf((a.y + s0.y) * di + b.y, 0.f);
        r.z = fmaxf((a.z + s0.z) * di + b.z, 0.f);
        r.w = fmaxf((a.w + s0.w) * di + b.w, 0.f);
        if (valid) h[q] = r;
        float4 wr = __ldg(&((const float4*)wroot)[q]);
        float4 wl = __ldg(&((const float4*)wrel)[q]);
        sr += r.x * wr.x + r.y * wr.y + r.z * wr.z + r.w * wr.w;
        st += r.x * wl.x + r.y * wl.y + r.z * wl.z + r.w * wl.w;
    }
    sr += __shfl_xor_sync(0xFFFFFFFFu, sr, 1);
    st += __shfl_xor_sync(0xFFFFFFFFu, st, 1);
    if (valid && half == 0) {
        d_score[i] = sr + __ldg(&pb[0]);
        d_t[i] = st;
    }
}

__global__ void k_scats1(const int* __restrict__ src, const int* __restrict__ dst) {
    int e = blockIdx.x * blockDim.x + threadIdx.x;
    if (e < Ee) atomicAdd(&d_score[dst[e]], __ldg(&d_t[src[e]]));
}

// ---------------- grid barrier + hist scan helpers -----------------------------
__device__ __forceinline__ void gbar(unsigned* bar, unsigned target) {
    __threadfence();
    __syncthreads();
    if (threadIdx.x == 0) {
        atomicAdd(bar, 1u);
        while (*((volatile unsigned*)bar) < target) {}
    }
    __syncthreads();
    __threadfence();
}

// nb must be >= 256 and a multiple of 256
__device__ __forceinline__ int scan_hist(const unsigned* gh, int nb, int& rem,
                                         unsigned* sh, volatile int* s_io) {
    for (int b = threadIdx.x; b < nb; b += 256) sh[b] = gh[b];
    __syncthreads();
    __shared__ unsigned part[256];
    int seg = nb >> 8;
    int base = threadIdx.x * seg;
    unsigned s = 0;
    for (int v = 0; v < seg; v++) s += sh[base + v];
    part[threadIdx.x] = s;
    __syncthreads();
    if (threadIdx.x == 0) {
        unsigned cum = 0;
        int t;
        for (t = 255; t >= 0; t--) {
            if (cum + part[t] >= (unsigned)rem) break;
            cum += part[t];
        }
        s_io[0] = t;
        s_io[1] = (int)cum;
    }
    __syncthreads();
    if ((int)threadIdx.x == s_io[0]) {
        int bb = s_io[0] * seg;
        unsigned cum = (unsigned)s_io[1];
        for (int v = seg - 1; v >= 0; v--) {
            unsigned c = sh[bb + v];
            cum += c;
            if (cum >= (unsigned)rem) {
                s_io[2] = bb + v;
                s_io[3] = rem - (int)(cum - c);
                break;
            }
        }
    }
    __syncthreads();
    int digit = s_io[2];
    rem = s_io[3];
    __syncthreads();
    return digit;
}

// ---------------- topk1: 3 passes (13+11+8 bits) + select + tie resolve --------
__device__ __forceinline__ void emit1(int p, int i) {
    d_perm[p] = i;
    atomicOr(&D_SELBIT[i >> 5], 1u << (i & 31));
    d_deg2[i] = 0;
    float th = tanhf(d_score[i]);
    const float4* h = (const float4*)&d_h[i * Hh];
    float4* o = (float4*)&d_x1[p * Hh];
#pragma unroll
    for (int q = 0; q < 4; q++) {
        float4 v = h[q];
        v.x *= th; v.y *= th; v.z *= th; v.w *= th;
        o[q] = v;
    }
}

__global__ void __launch_bounds__(256, 1) k_topk1() {
    __shared__ unsigned sh[8192];
    __shared__ int s_io[4];
    int gtid = blockIdx.x * 256 + threadIdx.x;
    const int NT = G1 * 256;
    int lane = threadIdx.x & 31;

    // pass 0: bits 31..19 (8192 bins), materialize 32-bit keys
    for (int b = threadIdx.x; b < 8192; b += 256) sh[b] = 0;
    __syncthreads();
    for (int i = gtid; i < Nn; i += NT) {
        unsigned u = f2u(d_score[i]);
        d_key32[i] = u;
        atomicAdd(&sh[u >> 19], 1u);
    }
    __syncthreads();
    for (int b = threadIdx.x; b < 8192; b += 256)
        if (sh[b]) atomicAdd(&HIST(0)[b], sh[b]);
    gbar(&D_STATE[0], G1);
    int rem = Kk1;
    int D1 = scan_hist(HIST(0), 8192, rem, sh, s_io);

    // pass 1: bits 18..8 (2048 bins)
    for (int b = threadIdx.x; b < 2048; b += 256) sh[b] = 0;
    __syncthreads();
    for (int i = gtid; i < Nn; i += NT) {
        unsigned u = d_key32[i];
        if ((int)(u >> 19) == D1) atomicAdd(&sh[(u >> 8) & 2047u], 1u);
    }
    __syncthreads();
    for (int b = threadIdx.x; b < 2048; b += 256)
        if (sh[b]) atomicAdd(&HIST(1)[b], sh[b]);
    gbar(&D_STATE[0], 2u * G1);
    int D2 = scan_hist(HIST(1), 2048, rem, sh, s_io);
    unsigned pre2 = ((unsigned)D1 << 11) | (unsigned)D2;

    // pass 2: bits 7..0 (256 bins)
    for (int b = threadIdx.x; b < 256; b += 256) sh[b] = 0;
    __syncthreads();
    for (int i = gtid; i < Nn; i += NT) {
        unsigned u = d_key32[i];
        if ((u >> 8) == pre2) atomicAdd(&sh[u & 255u], 1u);
    }
    __syncthreads();
    for (int b = threadIdx.x; b < 256; b += 256)
        if (sh[b]) atomicAdd(&HIST(2)[b], sh[b]);
    gbar(&D_STATE[0], 3u * G1);
    int D3 = scan_hist(HIST(2), 256, rem, sh, s_io);
    unsigned thr = (pre2 << 8) | (unsigned)D3;

    // select: key > thr emitted (warp-aggregated); key == thr goes to tie list
    for (int i = gtid; i - threadIdx.x < Nn; i += NT) {
        unsigned u = (i < Nn) ? d_key32[i] : 0u;
        bool sel = (i < Nn) && (u > thr);
        unsigned m = __ballot_sync(0xFFFFFFFFu, sel);
        if (m) {
            int leader = __ffs(m) - 1;
            int base = 0;
            if (lane == leader) base = atomicAdd((int*)&D_STATE[2], __popc(m));
            base = __shfl_sync(0xFFFFFFFFu, base, leader);
            if (sel) emit1(base + __popc(m & ((1u << lane) - 1u)), i);
        }
        if (i < Nn && u == thr) {
            int pos = atomicAdd((int*)&D_STATE[5], 1);
            if (pos < 32768) d_tie[pos] = i;
        }
    }
    gbar(&D_STATE[0], 4u * G1);

    // block 0: take the `rem` smallest node ids among ties (jax tie-break)
    if (blockIdx.x == 0) {
        int n = (int)D_STATE[5];
        if (n > 32768) n = 32768;
        for (int t = threadIdx.x; t < n; t += 256) {
            int idx = d_tie[t];
            int rank = 0;
            for (int u = 0; u < n; u++) rank += (d_tie[u] < idx);
            if (rank < rem) {
                int p = atomicAdd((int*)&D_STATE[2], 1);
                emit1(p, idx);
            }
        }
    }
}

__device__ __forceinline__ bool selbit(int i) {
    return (__ldg(&D_SELBIT[i >> 5]) >> (i & 31)) & 1u;
}

// ---------------- deg2 + edge compaction (block-aggregated reservation) --------
__global__ void k_deg2c(const int* __restrict__ src, const int* __restrict__ dst) {
    __shared__ int blk_cnt;
    __shared__ int blk_base;
    __shared__ int woff[8];
    int e = blockIdx.x * blockDim.x + threadIdx.x;
    int lane = threadIdx.x & 31, wid = threadIdx.x >> 5;
    if (threadIdx.x == 0) blk_cnt = 0;
    __syncthreads();
    int s = 0, d = 0;
    bool v = false;
    if (e < Ee) {
        s = src[e]; d = dst[e];
        v = selbit(s) && selbit(d);
    }
    unsigned m = __ballot_sync(0xFFFFFFFFu, v);
    if (v) atomicAdd(&d_deg2[d], 1);
    int wcnt = __popc(m);
    if (lane == 0 && wcnt) woff[wid] = atomicAdd(&blk_cnt, wcnt);
    __syncthreads();
    if (threadIdx.x == 0 && blk_cnt)
        blk_base = atomicAdd((int*)&D_STATE[3], blk_cnt);
    __syncthreads();
    if (v) {
        int pos = blk_base + woff[wid] + __popc(m & ((1u << lane) - 1u));
        d_eplist[pos] = ((unsigned long long)d << 32) | (unsigned)s;
    }
}

// ---------------- conv2: dinv2 + g0 = x1@W2 + self-loop init -------------------
__global__ void k_conv2(const float* __restrict__ W2, const float* __restrict__ b2) {
    int p = blockIdx.x * blockDim.x + threadIdx.x;
    if (p >= Kk1) return;
    int i = d_perm[p];
    float di = rsqrtf((float)d_deg2[i] + 1.0f);
    d_dinv2[i] = di;
    float s = di * di;
    float xr[Hh];
    const float4* xv = (const float4*)&d_x1[p * Hh];
#pragma unroll
    for (int q = 0; q < 4; q++) {
        float4 v = xv[q];
        xr[q*4] = v.x; xr[q*4+1] = v.y; xr[q*4+2] = v.z; xr[q*4+3] = v.w;
    }
    float* g = &d_g0[i * 16];
    float* h2 = &d_h2[i * 16];
#pragma unroll
    for (int j = 0; j < Cc; j++) {
        float a = 0.f;
#pragma unroll
        for (int f = 0; f < Hh; f++) a += xr[f] * __ldg(&W2[f * Cc + j]);
        g[j] = a;
        h2[j] = a * s + __ldg(&b2[j]);
    }
#pragma unroll
    for (int j = Cc; j < 16; j++) { g[j] = 0.f; h2[j] = 0.f; }
}

__global__ void k_scat2() {
    int ecnt = (int)D_STATE[3];
    for (int k = blockIdx.x * blockDim.x + threadIdx.x; k < ecnt;
         k += gridDim.x * blockDim.x) {
        unsigned long long pk = d_eplist[k];
        int s = (int)(pk & 0xFFFFFFFFu), d = (int)(pk >> 32);
        float nrm = __ldg(&d_dinv2[s]) * __ldg(&d_dinv2[d]);
        const float4* g = (const float4*)&d_g0[s * 16];
        float* a = &d_h2[d * 16];
#pragma unroll
        for (int q = 0; q < 3; q++) {
            float4 v = g[q];
            v.x *= nrm; v.y *= nrm; v.z *= nrm; v.w *= nrm;
            red_v4(a + q * 4, v);
        }
    }
}

__global__ void k_prep2(const float* __restrict__ wroot, const float* __restrict__ wrel,
                        const float* __restrict__ pb) {
    int p = blockIdx.x * blockDim.x + threadIdx.x;
    if (p >= Kk1) return;
    int i = d_perm[p];
    float sr = 0.f, st = 0.f;
#pragma unroll
    for (int j = 0; j < Cc; j++) {
        float v = d_h2[i * 16 + j];
        sr += v * __ldg(&wroot[j]);
        st += v * __ldg(&wrel[j]);
    }
    d_score2[i] = sr + __ldg(&pb[0]);
    d_t2[i] = st;
}

// ---------------- topk2: scats2 pre-phase + 3 passes + select + reduce ---------
__global__ void __launch_bounds__(256, 1) k_topk2(float* __restrict__ out) {
    __shared__ unsigned sh[8192];
    __shared__ int s_io[4];
    int gtid = blockIdx.x * 256 + threadIdx.x;
    const int NT = G2 * 256;

    // pre-phase: scats2 over packed edges
    int ecnt = (int)D_STATE[3];
    for (int k = gtid; k < ecnt; k += NT) {
        unsigned long long pk = d_eplist[k];
        int s = (int)(pk & 0xFFFFFFFFu), d = (int)(pk >> 32);
        atomicAdd(&d_score2[d], __ldg(&d_t2[s]));
    }
    gbar(&D_STATE[1], G2);

    // pass 0: bits 31..19
    for (int b = threadIdx.x; b < 8192; b += 256) sh[b] = 0;
    __syncthreads();
    for (int i = gtid; i < Kk1; i += NT) {
        unsigned u = f2u(__ldg(&d_score2[d_perm[i]]));
        d_key32[i] = u;
        atomicAdd(&sh[u >> 19], 1u);
    }
    __syncthreads();
    for (int b = threadIdx.x; b < 8192; b += 256)
        if (sh[b]) atomicAdd(&HIST(4)[b], sh[b]);
    gbar(&D_STATE[1], 2u * G2);
    int rem = Kk2;
    int D1 = scan_hist(HIST(4), 8192, rem, sh, s_io);

    // pass 1: bits 18..8
    for (int b = threadIdx.x; b < 2048; b += 256) sh[b] = 0;
    __syncthreads();
    for (int i = gtid; i < Kk1; i += NT) {
        unsigned u = d_key32[i];
        if ((int)(u >> 19) == D1) atomicAdd(&sh[(u >> 8) & 2047u], 1u);
    }
    __syncthreads();
    for (int b = threadIdx.x; b < 2048; b += 256)
        if (sh[b]) atomicAdd(&HIST(5)[b], sh[b]);
    gbar(&D_STATE[1], 3u * G2);
    int D2 = scan_hist(HIST(5), 2048, rem, sh, s_io);
    unsigned pre2 = ((unsigned)D1 << 11) | (unsigned)D2;

    // pass 2: bits 7..0
    for (int b = threadIdx.x; b < 256; b += 256) sh[b] = 0;
    __syncthreads();
    for (int i = gtid; i < Kk1; i += NT) {
        unsigned u = d_key32[i];
        if ((u >> 8) == pre2) atomicAdd(&sh[u & 255u], 1u);
    }
    __syncthreads();
    for (int b = threadIdx.x; b < 256; b += 256)
        if (sh[b]) atomicAdd(&HIST(6)[b], sh[b]);
    gbar(&D_STATE[1], 4u * G2);
    int D3 = scan_hist(HIST(6), 256, rem, sh, s_io);
    unsigned thr = (pre2 << 8) | (unsigned)D3;

    // select: accumulate key > thr; ties to list
    float acc[Cc];
#pragma unroll
    for (int j = 0; j < Cc; j++) acc[j] = 0.f;
    for (int i = gtid; i < Kk1; i += NT) {
        unsigned u = d_key32[i];
        if (u > thr) {
            int n = d_perm[i];
            float th = tanhf(d_score2[n]);
#pragma unroll
            for (int j = 0; j < Cc; j++) acc[j] += d_h2[n * 16 + j] * th;
        } else if (u == thr) {
            int pos = atomicAdd((int*)&D_STATE[6], 1);
            if (pos < 32768) d_tie[pos] = i;
        }
    }
#pragma unroll
    for (int o = 16; o; o >>= 1)
#pragma unroll
        for (int j = 0; j < Cc; j++) acc[j] += __shfl_xor_sync(0xFFFFFFFFu, acc[j], o);
    if ((threadIdx.x & 31) == 0)
#pragma unroll
        for (int j = 0; j < Cc; j++) atomicAdd(&D_ACC[j], acc[j]);
    gbar(&D_STATE[1], 5u * G2);

    // block 0: resolve ties (rem smallest perm positions), then final output
    if (blockIdx.x == 0) {
        int n = (int)D_STATE[6];
        if (n > 32768) n = 32768;
        for (int t = threadIdx.x; t < n; t += 256) {
            int i = d_tie[t];
            int rank = 0;
            for (int u = 0; u < n; u++) rank += (d_tie[u] < i);
            if (rank < rem) {
                int nn = d_perm[i];
                float th = tanhf(d_score2[nn]);
#pragma unroll
                for (int j = 0; j < Cc; j++)
                    atomicAdd(&D_ACC[j], d_h2[nn * 16 + j] * th);
            }
        }
        __threadfence();
        __syncthreads();
        if (threadIdx.x == 0) {
            float m[Cc], mx = -1e30f;
#pragma unroll
            for (int j = 0; j < Cc; j++) {
                m[j] = D_ACC[j] / (float)Kk2;
                mx = fmaxf(mx, m[j]);
            }
            float lse = 0.f;
#pragma unroll
            for (int j = 0; j < Cc; j++) lse += expf(m[j] - mx);
            lse = logf(lse);
#pragma unroll
            for (int j = 0; j < Cc; j++) out[j] = m[j] - mx - lse;
        }
    }
}

// ---------------- launch --------------------------------------------------------
extern "C" void kernel_launch(void* const* d_in, const int* in_sizes, int n_in,
                              void* d_out, int out_size) {
    const float* x = (const float*)d_in[0];
    const int* esrc = (const int*)d_in[1];
    const int* edst = (const int*)d_in[2];
    const float* W1 = (const float*)d_in[3];
    const float* b1 = (const float*)d_in[4];
    const float* p1wr = (const float*)d_in[5];
    const float* p1wl = (const float*)d_in[6];
    const float* p1b = (const float*)d_in[7];
    const float* W2 = (const float*)d_in[8];
    const float* b2 = (const float*)d_in[9];
    const float* p2wr = (const float*)d_in[10];
    const float* p2wl = (const float*)d_in[11];
    const float* p2b = (const float*)d_in[12];
    float* out = (float*)d_out;

    void *p_h, *p_deg, *p_blob;
    cudaGetSymbolAddress(&p_h, d_h);
    cudaGetSymbolAddress(&p_deg, d_deg);
    cudaGetSymbolAddress(&p_blob, d_blob);
    cudaMemsetAsync(p_h, 0, Nn * Hh * sizeof(float));
    cudaMemsetAsync(p_deg, 0, Nn * sizeof(int));
    cudaMemsetAsync(p_blob, 0, 68696 * sizeof(unsigned));

    const int T = 256;
    k_front<<<MM1_BLOCKS + DEG_BLOCKS, T>>>(x, W1, edst);
    k_dinv<<<(2 * Nn + T - 1) / T, T>>>();
    k_scat1<<<(Ee * 4) / T, T>>>(esrc, edst);
    k_prep1<<<(2 * Nn + T - 1) / T, T>>>(b1, p1wr, p1wl, p1b);
    k_scats1<<<(Ee + T - 1) / T, T>>>(esrc, edst);
    k_topk1<<<G1, 256>>>();
    k_deg2c<<<(Ee + T - 1) / T, T>>>(esrc, edst);
    k_conv2<<<(Kk1 + T - 1) / T, T>>>(W2, b2);
    k_scat2<<<416, T>>>();
    k_prep2<<<(Kk1 + T - 1) / T, T>>>(p2wr, p2wl, p2b);
    k_topk2<<<G2, 256>>>(out);
}

// round 17
// speedup vs baseline: 1.3391x; 1.0079x over previous
#include <cuda_runtime.h>
#include <math.h>

#define Nn 100000
#define Ee 3200000
#define Ff 128
#define Hh 16
#define Cc 10
#define Kk1 25000
#define Kk2 6250
#define G1 148    // topk1 persistent grid
#define G2 74     // topk2 persistent grid

// ---------------- scratch ------------------------------------------------------
__device__ __align__(16) float d_h0[Nn * Hh];   // x@W1, then scaled by dinv
__device__ __align__(16) float d_h[Nn * Hh];    // conv1 edge accumulator (memset 0)
__device__ float d_dinv[Nn];
__device__ int d_deg[Nn];                        // memset 0
__device__ float d_t[Nn];
__device__ float d_score[Nn];
__device__ unsigned d_key32[Nn];
__device__ int d_perm[Kk1];
__device__ int d_deg2[Nn];
__device__ float d_dinv2[Nn];
__device__ __align__(16) float d_x1[Kk1 * Hh];
__device__ __align__(16) float d_g0[Nn * 16];
__device__ __align__(16) float d_h2[Nn * 16];
__device__ float d_t2[Nn];
__device__ float d_score2[Nn];
__device__ unsigned long long d_eplist[Ee];
__device__ int d_tie[32768];

// one zeroed blob: hist[8][8192] | selbit[3136] | state[8] | acc[10]
__device__ __align__(16) unsigned d_blob[68696];
#define HIST(p) (d_blob + (p) * 8192)
#define D_SELBIT (d_blob + 65536)
#define D_STATE (d_blob + 68672)  // 0:bar1 1:bar2 2:permcnt 3:ecnt 4:- 5:tie1 6:tie2
#define D_ACC ((float*)(d_blob + 68680))

__device__ __forceinline__ void red_v4(float* p, float4 v) {
    asm volatile("red.global.add.v4.f32 [%0], {%1,%2,%3,%4};"
                 :: "l"(p), "f"(v.x), "f"(v.y), "f"(v.z), "f"(v.w) : "memory");
}
__device__ __forceinline__ unsigned f2u(float f) {
    unsigned u = __float_as_uint(f);
    return (u & 0x80000000u) ? ~u : (u | 0x80000000u);
}

// ---------------- fused: h0 = x @ W1 (grid-stride warps)  ||  deg count --------
#define MM1_BLOCKS 1536
#define DEG_BLOCKS 1024
__global__ void k_front(const float* __restrict__ x, const float* __restrict__ W1,
                        const int* __restrict__ dst) {
    if (blockIdx.x < MM1_BLOCKS) {
        __shared__ float Ws[Ff * Hh];
        for (int i = threadIdx.x; i < Ff * Hh; i += blockDim.x) Ws[i] = W1[i];
        __syncthreads();
        int lane = threadIdx.x & 31;
        for (int node = blockIdx.x * 8 + (threadIdx.x >> 5); node < Nn;
             node += MM1_BLOCKS * 8) {
            const float* xr = x + (size_t)node * Ff;
            float acc[Hh];
#pragma unroll
            for (int j = 0; j < Hh; j++) acc[j] = 0.f;
#pragma unroll
            for (int c = 0; c < 4; c++) {
                int f = c * 32 + lane;
                float xv = xr[f];
                const float* wr = Ws + f * Hh;
#pragma unroll
                for (int j = 0; j < Hh; j++) acc[j] += xv * wr[j];
            }
            // column-folding reduction: 17 SHFL instead of 80.
            {
                bool hi = (lane & 16) != 0;
#pragma unroll
                for (int j = 0; j < 8; j++) {
                    float sent = hi ? acc[j] : acc[j + 8];
                    float recv = __shfl_xor_sync(0xFFFFFFFFu, sent, 16);
                    acc[j] = (hi ? acc[j + 8] : acc[j]) + recv;
                }
            }
            {
                bool hi = (lane & 8) != 0;
#pragma unroll
                for (int j = 0; j < 4; j++) {
                    float sent = hi ? acc[j] : acc[j + 4];
                    float recv = __shfl_xor_sync(0xFFFFFFFFu, sent, 8);
                    acc[j] = (hi ? acc[j + 4] : acc[j]) + recv;
                }
            }
            {
                bool hi = (lane & 4) != 0;
#pragma unroll
                for (int j = 0; j < 2; j++) {
                    float sent = hi ? acc[j] : acc[j + 2];
                    float recv = __shfl_xor_sync(0xFFFFFFFFu, sent, 4);
                    acc[j] = (hi ? acc[j + 2] : acc[j]) + recv;
                }
            }
            {
                bool hi = (lane & 2) != 0;
                float sent = hi ? acc[0] : acc[1];
                float recv = __shfl_xor_sync(0xFFFFFFFFu, sent, 2);
                acc[0] = (hi ? acc[1] : acc[0]) + recv;
            }
            acc[0] += __shfl_xor_sync(0xFFFFFFFFu, acc[0], 1);
            float colv = __shfl_sync(0xFFFFFFFFu, acc[0], (lane << 1) & 31);
            if (lane < Hh) d_h0[(size_t)node * Hh + lane] = colv;
        }
    } else {
        for (int e = (blockIdx.x - MM1_BLOCKS) * 256 + threadIdx.x; e < Ee;
             e += DEG_BLOCKS * 256)
            atomicAdd(&d_deg[dst[e]], 1);
    }
}

// dinv + pre-scale h0 (2 threads per node)
__global__ void k_dinv() {
    int gid = blockIdx.x * blockDim.x + threadIdx.x;
    int i = gid >> 1, half = gid & 1;
    bool valid = i < Nn;
    if (!valid) i = Nn - 1;
    float di = rsqrtf((float)d_deg[i] + 1.0f);
    if (valid && half == 0) d_dinv[i] = di;
    float4* h0 = (float4*)&d_h0[i * Hh];
#pragma unroll
    for (int qq = 0; qq < 2; qq++) {
        int q = half * 2 + qq;
        float4 v = h0[q];
        v.x *= di; v.y *= di; v.z *= di; v.w *= di;
        if (valid) h0[q] = v;
    }
}

__global__ void k_scat1(const int* __restrict__ src, const int* __restrict__ dst) {
    int t = blockIdx.x * blockDim.x + threadIdx.x;
    int e = t >> 2, q = t & 3;
    int s = src[e], d = dst[e];
    float4 v = *(const float4*)&d_h0[s * Hh + q * 4];
    red_v4(&d_h[d * Hh + q * 4], v);
}

// finalize conv1 (2 threads per node)
__global__ void k_prep1(const float* __restrict__ b1, const float* __restrict__ wroot,
                        const float* __restrict__ wrel, const float* __restrict__ pb) {
    int gid = blockIdx.x * blockDim.x + threadIdx.x;
    int i = gid >> 1, half = gid & 1;
    bool valid = i < Nn;
    if (!valid) i = Nn - 1;
    float di = d_dinv[i];
    float4* h = (float4*)&d_h[i * Hh];
    const float4* h0 = (const float4*)&d_h0[i * Hh];
    float sr = 0.f, st = 0.f;
#pragma unroll
    for (int qq = 0; qq < 2; qq++) {
        int q = half * 2 + qq;
        float4 a = h[q], s0 = h0[q];
        float4 b = __ldg(&((const float4*)b1)[q]);
        float4 r;
        r.x = fmaxf((a.x + s0.x) * di + b.x, 0.f);
        r.y = fmaxf((a.y + s0.y) * di + b.y, 0.f);
        r.z = fmaxf((a.z + s0.z) * di + b.z, 0.f);
        r.w = fmaxf((a.w + s0.w) * di + b.w, 0.f);
        if (valid) h[q] = r;
        float4 wr = __ldg(&((const float4*)wroot)[q]);
        float4 wl = __ldg(&((const float4*)wrel)[q]);
        sr += r.x * wr.x + r.y * wr.y + r.z * wr.z + r.w * wr.w;
        st += r.x * wl.x + r.y * wl.y + r.z * wl.z + r.w * wl.w;
    }
    sr += __shfl_xor_sync(0xFFFFFFFFu, sr, 1);
    st += __shfl_xor_sync(0xFFFFFFFFu, st, 1);
    if (valid && half == 0) {
        d_score[i] = sr + __ldg(&pb[0]);
        d_t[i] = st;
    }
}

__global__ void k_scats1(const int* __restrict__ src, const int* __restrict__ dst) {
    int e = blockIdx.x * blockDim.x + threadIdx.x;
    if (e < Ee) atomicAdd(&d_score[dst[e]], __ldg(&d_t[src[e]]));
}

// ---------------- grid barrier + hist scan helpers -----------------------------
__device__ __forceinline__ void gbar(unsigned* bar, unsigned target) {
    __threadfence();
    __syncthreads();
    if (threadIdx.x == 0) {
        atomicAdd(bar, 1u);
        while (*((volatile unsigned*)bar) < target) {}
    }
    __syncthreads();
    __threadfence();
}

// nb must be >= 256 and a multiple of 256
__device__ __forceinline__ int scan_hist(const unsigned* gh, int nb, int& rem,
                                         unsigned* sh, volatile int* s_io) {
    for (int b = threadIdx.x; b < nb; b += 256) sh[b] = gh[b];
    __syncthreads();
    __shared__ unsigned part[256];
    int seg = nb >> 8;
    int base = threadIdx.x * seg;
    unsigned s = 0;
    for (int v = 0; v < seg; v++) s += sh[base + v];
    part[threadIdx.x] = s;
    __syncthreads();
    if (threadIdx.x == 0) {
        unsigned cum = 0;
        int t;
        for (t = 255; t >= 0; t--) {
            if (cum + part[t] >= (unsigned)rem) break;
            cum += part[t];
        }
        s_io[0] = t;
        s_io[1] = (int)cum;
    }
    __syncthreads();
    if ((int)threadIdx.x == s_io[0]) {
        int bb = s_io[0] * seg;
        unsigned cum = (unsigned)s_io[1];
        for (int v = seg - 1; v >= 0; v--) {
            unsigned c = sh[bb + v];
            cum += c;
            if (cum >= (unsigned)rem) {
                s_io[2] = bb + v;
                s_io[3] = rem - (int)(cum - c);
                break;
            }
        }
    }
    __syncthreads();
    int digit = s_io[2];
    rem = s_io[3];
    __syncthreads();
    return digit;
}

// ---------------- topk1: 3 passes (13+11+8 bits) + select + tie resolve --------
__device__ __forceinline__ void emit1(int p, int i) {
    d_perm[p] = i;
    atomicOr(&D_SELBIT[i >> 5], 1u << (i & 31));
    d_deg2[i] = 0;
    float th = tanhf(d_score[i]);
    const float4* h = (const float4*)&d_h[i * Hh];
    float4* o = (float4*)&d_x1[p * Hh];
#pragma unroll
    for (int q = 0; q < 4; q++) {
        float4 v = h[q];
        v.x *= th; v.y *= th; v.z *= th; v.w *= th;
        o[q] = v;
    }
}

__global__ void __launch_bounds__(256, 1) k_topk1() {
    __shared__ unsigned sh[8192];
    __shared__ int s_io[4];
    int gtid = blockIdx.x * 256 + threadIdx.x;
    const int NT = G1 * 256;
    int lane = threadIdx.x & 31;

    // pass 0: bits 31..19 (8192 bins), materialize 32-bit keys
    for (int b = threadIdx.x; b < 8192; b += 256) sh[b] = 0;
    __syncthreads();
    for (int i = gtid; i < Nn; i += NT) {
        unsigned u = f2u(d_score[i]);
        d_key32[i] = u;
        atomicAdd(&sh[u >> 19], 1u);
    }
    __syncthreads();
    for (int b = threadIdx.x; b < 8192; b += 256)
        if (sh[b]) atomicAdd(&HIST(0)[b], sh[b]);
    gbar(&D_STATE[0], G1);
    int rem = Kk1;
    int D1 = scan_hist(HIST(0), 8192, rem, sh, s_io);

    // pass 1: bits 18..8 (2048 bins)
    for (int b = threadIdx.x; b < 2048; b += 256) sh[b] = 0;
    __syncthreads();
    for (int i = gtid; i < Nn; i += NT) {
        unsigned u = d_key32[i];
        if ((int)(u >> 19) == D1) atomicAdd(&sh[(u >> 8) & 2047u], 1u);
    }
    __syncthreads();
    for (int b = threadIdx.x; b < 2048; b += 256)
        if (sh[b]) atomicAdd(&HIST(1)[b], sh[b]);
    gbar(&D_STATE[0], 2u * G1);
    int D2 = scan_hist(HIST(1), 2048, rem, sh, s_io);
    unsigned pre2 = ((unsigned)D1 << 11) | (unsigned)D2;

    // pass 2: bits 7..0 (256 bins)
    for (int b = threadIdx.x; b < 256; b += 256) sh[b] = 0;
    __syncthreads();
    for (int i = gtid; i < Nn; i += NT) {
        unsigned u = d_key32[i];
        if ((u >> 8) == pre2) atomicAdd(&sh[u & 255u], 1u);
    }
    __syncthreads();
    for (int b = threadIdx.x; b < 256; b += 256)
        if (sh[b]) atomicAdd(&HIST(2)[b], sh[b]);
    gbar(&D_STATE[0], 3u * G1);
    int D3 = scan_hist(HIST(2), 256, rem, sh, s_io);
    unsigned thr = (pre2 << 8) | (unsigned)D3;

    // select: key > thr emitted (warp-aggregated); key == thr goes to tie list
    for (int i = gtid; i - threadIdx.x < Nn; i += NT) {
        unsigned u = (i < Nn) ? d_key32[i] : 0u;
        bool sel = (i < Nn) && (u > thr);
        unsigned m = __ballot_sync(0xFFFFFFFFu, sel);
        if (m) {
            int leader = __ffs(m) - 1;
            int base = 0;
            if (lane == leader) base = atomicAdd((int*)&D_STATE[2], __popc(m));
            base = __shfl_sync(0xFFFFFFFFu, base, leader);
            if (sel) emit1(base + __popc(m & ((1u << lane) - 1u)), i);
        }
        if (i < Nn && u == thr) {
            int pos = atomicAdd((int*)&D_STATE[5], 1);
            if (pos < 32768) d_tie[pos] = i;
        }
    }
    gbar(&D_STATE[0], 4u * G1);

    // block 0: take the `rem` smallest node ids among ties (jax tie-break)
    if (blockIdx.x == 0) {
        int n = (int)D_STATE[5];
        if (n > 32768) n = 32768;
        for (int t = threadIdx.x; t < n; t += 256) {
            int idx = d_tie[t];
            int rank = 0;
            for (int u = 0; u < n; u++) rank += (d_tie[u] < idx);
            if (rank < rem) {
                int p = atomicAdd((int*)&D_STATE[2], 1);
                emit1(p, idx);
            }
        }
    }
}

__device__ __forceinline__ bool selbit(int i) {
    return (__ldg(&D_SELBIT[i >> 5]) >> (i & 31)) & 1u;
}

// ---------------- deg2 + edge compaction (block-aggregated reservation) --------
__global__ void k_deg2c(const int* __restrict__ src, const int* __restrict__ dst) {
    __shared__ int blk_cnt;
    __shared__ int blk_base;
    __shared__ int woff[8];
    int e = blockIdx.x * blockDim.x + threadIdx.x;
    int lane = threadIdx.x & 31, wid = threadIdx.x >> 5;
    if (threadIdx.x == 0) blk_cnt = 0;
    __syncthreads();
    int s = 0, d = 0;
    bool v = false;
    if (e < Ee) {
        s = src[e]; d = dst[e];
        v = selbit(s) && selbit(d);
    }
    unsigned m = __ballot_sync(0xFFFFFFFFu, v);
    if (v) atomicAdd(&d_deg2[d], 1);
    int wcnt = __popc(m);
    if (lane == 0 && wcnt) woff[wid] = atomicAdd(&blk_cnt, wcnt);
    __syncthreads();
    if (threadIdx.x == 0 && blk_cnt)
        blk_base = atomicAdd((int*)&D_STATE[3], blk_cnt);
    __syncthreads();
    if (v) {
        int pos = blk_base + woff[wid] + __popc(m & ((1u << lane) - 1u));
        d_eplist[pos] = ((unsigned long long)d << 32) | (unsigned)s;
    }
}

// ---------------- conv2: dinv2 + g0 = x1@W2 + self-loop init -------------------
__global__ void k_conv2(const float* __restrict__ W2, const float* __restrict__ b2) {
    int p = blockIdx.x * blockDim.x + threadIdx.x;
    if (p >= Kk1) return;
    int i = d_perm[p];
    float di = rsqrtf((float)d_deg2[i] + 1.0f);
    d_dinv2[i] = di;
    float s = di * di;
    float xr[Hh];
    const float4* xv = (const float4*)&d_x1[p * Hh];
#pragma unroll
    for (int q = 0; q < 4; q++) {
        float4 v = xv[q];
        xr[q*4] = v.x; xr[q*4+1] = v.y; xr[q*4+2] = v.z; xr[q*4+3] = v.w;
    }
    float* g = &d_g0[i * 16];
    float* h2 = &d_h2[i * 16];
#pragma unroll
    for (int j = 0; j < Cc; j++) {
        float a = 0.f;
#pragma unroll
        for (int f = 0; f < Hh; f++) a += xr[f] * __ldg(&W2[f * Cc + j]);
        g[j] = a;
        h2[j] = a * s + __ldg(&b2[j]);
    }
#pragma unroll
    for (int j = Cc; j < 16; j++) { g[j] = 0.f; h2[j] = 0.f; }
}

// ---------------- topk2: scat2+prep2+scats2 pre-phases + 3 passes + reduce -----
__global__ void __launch_bounds__(256, 1) k_topk2(
    const float* __restrict__ wroot, const float* __restrict__ wrel,
    const float* __restrict__ pb, float* __restrict__ out) {
    __shared__ unsigned sh[8192];
    __shared__ int s_io[4];
    int gtid = blockIdx.x * 256 + threadIdx.x;
    const int NT = G2 * 256;
    unsigned barN = 0;
    int ecnt = (int)D_STATE[3];

    // pre-phase A: scat2 over packed edges
    for (int k = gtid; k < ecnt; k += NT) {
        unsigned long long pk = d_eplist[k];
        int s = (int)(pk & 0xFFFFFFFFu), d = (int)(pk >> 32);
        float nrm = __ldg(&d_dinv2[s]) * __ldg(&d_dinv2[d]);
        const float4* g = (const float4*)&d_g0[s * 16];
        float* a = &d_h2[d * 16];
#pragma unroll
        for (int q = 0; q < 3; q++) {
            float4 v = g[q];
            v.x *= nrm; v.y *= nrm; v.z *= nrm; v.w *= nrm;
            red_v4(a + q * 4, v);
        }
    }
    barN += G2; gbar(&D_STATE[1], barN);

    // pre-phase B: prep2 (score2/t2)
    for (int p = gtid; p < Kk1; p += NT) {
        int i = d_perm[p];
        float sr = 0.f, st = 0.f;
#pragma unroll
        for (int j = 0; j < Cc; j++) {
            float v = d_h2[i * 16 + j];
            sr += v * __ldg(&wroot[j]);
            st += v * __ldg(&wrel[j]);
        }
        d_score2[i] = sr + __ldg(&pb[0]);
        d_t2[i] = st;
    }
    barN += G2; gbar(&D_STATE[1], barN);

    // pre-phase C: scats2
    for (int k = gtid; k < ecnt; k += NT) {
        unsigned long long pk = d_eplist[k];
        int s = (int)(pk & 0xFFFFFFFFu), d = (int)(pk >> 32);
        atomicAdd(&d_score2[d], __ldg(&d_t2[s]));
    }
    barN += G2; gbar(&D_STATE[1], barN);

    // pass 0: bits 31..19
    for (int b = threadIdx.x; b < 8192; b += 256) sh[b] = 0;
    __syncthreads();
    for (int i = gtid; i < Kk1; i += NT) {
        unsigned u = f2u(__ldg(&d_score2[d_perm[i]]));
        d_key32[i] = u;
        atomicAdd(&sh[u >> 19], 1u);
    }
    __syncthreads();
    for (int b = threadIdx.x; b < 8192; b += 256)
        if (sh[b]) atomicAdd(&HIST(4)[b], sh[b]);
    barN += G2; gbar(&D_STATE[1], barN);
    int rem = Kk2;
    int D1 = scan_hist(HIST(4), 8192, rem, sh, s_io);

    // pass 1: bits 18..8
    for (int b = threadIdx.x; b < 2048; b += 256) sh[b] = 0;
    __syncthreads();
    for (int i = gtid; i < Kk1; i += NT) {
        unsigned u = d_key32[i];
        if ((int)(u >> 19) == D1) atomicAdd(&sh[(u >> 8) & 2047u], 1u);
    }
    __syncthreads();
    for (int b = threadIdx.x; b < 2048; b += 256)
        if (sh[b]) atomicAdd(&HIST(5)[b], sh[b]);
    barN += G2; gbar(&D_STATE[1], barN);
    int D2 = scan_hist(HIST(5), 2048, rem, sh, s_io);
    unsigned pre2 = ((unsigned)D1 << 11) | (unsigned)D2;

    // pass 2: bits 7..0
    for (int b = threadIdx.x; b < 256; b += 256) sh[b] = 0;
    __syncthreads();
    for (int i = gtid; i < Kk1; i += NT) {
        unsigned u = d_key32[i];
        if ((u >> 8) == pre2) atomicAdd(&sh[u & 255u], 1u);
    }
    __syncthreads();
    for (int b = threadIdx.x; b < 256; b += 256)
        if (sh[b]) atomicAdd(&HIST(6)[b], sh[b]);
    barN += G2; gbar(&D_STATE[1], barN);
    int D3 = scan_hist(HIST(6), 256, rem, sh, s_io);
    unsigned thr = (pre2 << 8) | (unsigned)D3;

    // select: accumulate key > thr; ties to list
    float acc[Cc];
#pragma unroll
    for (int j = 0; j < Cc; j++) acc[j] = 0.f;
    for (int i = gtid; i < Kk1; i += NT) {
        unsigned u = d_key32[i];
        if (u > thr) {
            int n = d_perm[i];
            float th = tanhf(d_score2[n]);
#pragma unroll
            for (int j = 0; j < Cc; j++) acc[j] += d_h2[n * 16 + j] * th;
        } else if (u == thr) {
            int pos = atomicAdd((int*)&D_STATE[6], 1);
            if (pos < 32768) d_tie[pos] = i;
        }
    }
#pragma unroll
    for (int o = 16; o; o >>= 1)
#pragma unroll
        for (int j = 0; j < Cc; j++) acc[j] += __shfl_xor_sync(0xFFFFFFFFu, acc[j], o);
    if ((threadIdx.x & 31) == 0)
#pragma unroll
        for (int j = 0; j < Cc; j++) atomicAdd(&D_ACC[j], acc[j]);
    barN += G2; gbar(&D_STATE[1], barN);

    // block 0: resolve ties (rem smallest perm positions), then final output
    if (blockIdx.x == 0) {
        int n = (int)D_STATE[6];
        if (n > 32768) n = 32768;
        for (int t = threadIdx.x; t < n; t += 256) {
            int i = d_tie[t];
            int rank = 0;
            for (int u = 0; u < n; u++) rank += (d_tie[u] < i);
            if (rank < rem) {
                int nn = d_perm[i];
                float th = tanhf(d_score2[nn]);
#pragma unroll
                for (int j = 0; j < Cc; j++)
                    atomicAdd(&D_ACC[j], d_h2[nn * 16 + j] * th);
            }
        }
        __threadfence();
        __syncthreads();
        if (threadIdx.x == 0) {
            float m[Cc], mx = -1e30f;
#pragma unroll
            for (int j = 0; j < Cc; j++) {
                m[j] = D_ACC[j] / (float)Kk2;
                mx = fmaxf(mx, m[j]);
            }
            float lse = 0.f;
#pragma unroll
            for (int j = 0; j < Cc; j++) lse += expf(m[j] - mx);
            lse = logf(lse);
#pragma unroll
            for (int j = 0; j < Cc; j++) out[j] = m[j] - mx - lse;
        }
    }
}

// ---------------- launch --------------------------------------------------------
extern "C" void kernel_launch(void* const* d_in, const int* in_sizes, int n_in,
                              void* d_out, int out_size) {
    const float* x = (const float*)d_in[0];
    const int* esrc = (const int*)d_in[1];
    const int* edst = (const int*)d_in[2];
    const float* W1 = (const float*)d_in[3];
    const float* b1 = (const float*)d_in[4];
    const float* p1wr = (const float*)d_in[5];
    const float* p1wl = (const float*)d_in[6];
    const float* p1b = (const float*)d_in[7];
    const float* W2 = (const float*)d_in[8];
    const float* b2 = (const float*)d_in[9];
    const float* p2wr = (const float*)d_in[10];
    const float* p2wl = (const float*)d_in[11];
    const float* p2b = (const float*)d_in[12];
    float* out = (float*)d_out;

    void *p_h, *p_deg, *p_blob;
    cudaGetSymbolAddress(&p_h, d_h);
    cudaGetSymbolAddress(&p_deg, d_deg);
    cudaGetSymbolAddress(&p_blob, d_blob);
    cudaMemsetAsync(p_h, 0, Nn * Hh * sizeof(float));
    cudaMemsetAsync(p_deg, 0, Nn * sizeof(int));
    cudaMemsetAsync(p_blob, 0, 68696 * sizeof(unsigned));

    const int T = 256;
    k_front<<<MM1_BLOCKS + DEG_BLOCKS, T>>>(x, W1, edst);
    k_dinv<<<(2 * Nn + T - 1) / T, T>>>();
    k_scat1<<<(Ee * 4) / T, T>>>(esrc, edst);
    k_prep1<<<(2 * Nn + T - 1) / T, T>>>(b1, p1wr, p1wl, p1b);
    k_scats1<<<(Ee + T - 1) / T, T>>>(esrc, edst);
    k_topk1<<<G1, 256>>>();
    k_deg2c<<<(Ee + T - 1) / T, T>>>(esrc, edst);
    k_conv2<<<(Kk1 + T - 1) / T, T>>>(W2, b2);
    k_topk2<<<G2, 256>>>(p2wr, p2wl, p2b, out);
}